// round 7
// baseline (speedup 1.0000x reference)
#include <cuda_runtime.h>

// RNNModel: x[8192,512,8] fp32 -> out[8192] fp32.
// R6: 4-lane groups, TWO batch elements per thread (shared weights) -> 8
// independent FMA2 chains per warp; proj and recur accumulate separately
// (chain 8 / chain 16) and combine with one add.f32x2. 512 warps, 1/SMSP.

constexpr int T_LEN = 512;
constexpr int I_LEN = 8;
constexpr int H_LEN = 16;
constexpr int CHUNK = 2;                  // steps per buffer per batch
constexpr int NCHUNK = T_LEN / CHUNK;     // 256

typedef unsigned long long ull;

__device__ __forceinline__ ull ffma2(ull a, ull b, ull c) {
    ull d;
    asm("fma.rn.f32x2 %0, %1, %2, %3;" : "=l"(d) : "l"(a), "l"(b), "l"(c));
    return d;
}
__device__ __forceinline__ ull fadd2(ull a, ull b) {
    ull d;
    asm("add.rn.f32x2 %0, %1, %2;" : "=l"(d) : "l"(a), "l"(b));
    return d;
}
__device__ __forceinline__ ull dup2(float v) {
    ull d;
    asm("mov.b64 %0, {%1, %1};" : "=l"(d) : "f"(v));
    return d;
}
__device__ __forceinline__ ull pack2(float x, float y) {
    ull d;
    asm("mov.b64 %0, {%1, %2};" : "=l"(d) : "f"(x), "f"(y));
    return d;
}
__device__ __forceinline__ void unpack2(ull d, float& x, float& y) {
    asm("mov.b64 {%0, %1}, %2;" : "=f"(x), "=f"(y) : "l"(d));
}

// v pre-scaled by 2*log2(e): tanh = 1 - 2/(ex2(v)+1). ~1e-7 abs err.
__device__ __forceinline__ float tanh_pre(float v) {
    float e, r;
    asm("ex2.approx.f32 %0, %1;" : "=f"(e) : "f"(v));
    asm("rcp.approx.f32 %0, %1;" : "=f"(r) : "f"(e + 1.0f));
    return fmaf(-2.0f, r, 1.0f);
}

__global__ void __launch_bounds__(128) rnn_fused6_kernel(
    const float* __restrict__ x,
    const float* __restrict__ W_ih,
    const float* __restrict__ W_hh,
    const float* __restrict__ b_ih,
    const float* __restrict__ b_hh,
    const float* __restrict__ fc_w,
    const float* __restrict__ fc_b,
    float* __restrict__ out,
    int n_batch)
{
    const int tid = blockIdx.x * blockDim.x + threadIdx.x;
    const int sub = tid & 3;          // lane within 4-lane group
    const int g   = tid >> 2;         // group index
    const int b0  = 2 * g;            // first batch element
    const int b1  = 2 * g + 1;        // second batch element
    if (b1 >= n_batch) return;
    const int c0 = sub * 4;           // own channel base

    const float C = 2.8853900817779268f;  // 2*log2(e) folded into weights

    // Shared (per-thread) weight slices — identical for both batches.
    // w[p][m][k]: scaled W_hh column (channel 4*(sub^m)+k) for output pair p.
    ull w[2][4][4];
#pragma unroll
    for (int p = 0; p < 2; p++) {
        const int r0 = (c0 + 2 * p) * H_LEN;
        const int r1 = r0 + H_LEN;
#pragma unroll
        for (int m = 0; m < 4; m++) {
            const int cb = 4 * (sub ^ m);
#pragma unroll
            for (int k = 0; k < 4; k++)
                w[p][m][k] = pack2(C * W_hh[r0 + cb + k], C * W_hh[r1 + cb + k]);
        }
    }
    ull u[2][I_LEN];
#pragma unroll
    for (int p = 0; p < 2; p++) {
        const int r0 = (c0 + 2 * p) * I_LEN;
        const int r1 = r0 + I_LEN;
#pragma unroll
        for (int i = 0; i < I_LEN; i++)
            u[p][i] = pack2(C * W_ih[r0 + i], C * W_ih[r1 + i]);
    }
    ull bias[2];
#pragma unroll
    for (int p = 0; p < 2; p++)
        bias[p] = pack2(C * (b_ih[c0 + 2 * p]     + b_hh[c0 + 2 * p]),
                        C * (b_ih[c0 + 2 * p + 1] + b_hh[c0 + 2 * p + 1]));

    float h0[4] = {0.f, 0.f, 0.f, 0.f};   // batch b0's own channels
    float h1[4] = {0.f, 0.f, 0.f, 0.f};   // batch b1's own channels

    const float4* xb0 = reinterpret_cast<const float4*>(x + (size_t)b0 * T_LEN * I_LEN);
    const float4* xb1 = reinterpret_cast<const float4*>(x + (size_t)b1 * T_LEN * I_LEN);

    // One timestep for BOTH batches. proj accumulates into pa (8-link chains,
    // off the h critical path); recur into ra (16-link chains from h/shfl);
    // combined once with add.f32x2 before tanh.
    auto stepPair = [&](float4 x00, float4 x01, float4 x10, float4 x11) {
        // -- input projections (independent of h) --
        ull pa00 = bias[0], pa01 = bias[1], pa10 = bias[0], pa11 = bias[1];
        {
            const float xs0[8] = {x00.x, x00.y, x00.z, x00.w, x01.x, x01.y, x01.z, x01.w};
            const float xs1[8] = {x10.x, x10.y, x10.z, x10.w, x11.x, x11.y, x11.z, x11.w};
#pragma unroll
            for (int i = 0; i < I_LEN; i++) {
                const ull d0 = dup2(xs0[i]);
                pa00 = ffma2(d0, u[0][i], pa00);
                pa01 = ffma2(d0, u[1][i], pa01);
                const ull d1 = dup2(xs1[i]);
                pa10 = ffma2(d1, u[0][i], pa10);
                pa11 = ffma2(d1, u[1][i], pa11);
            }
        }
        // -- gather partner h for both batches --
        float rv0[3][4], rv1[3][4];
#pragma unroll
        for (int m = 1; m < 4; m++)
#pragma unroll
            for (int k = 0; k < 4; k++) {
                rv0[m - 1][k] = __shfl_xor_sync(0xffffffffu, h0[k], m);
                rv1[m - 1][k] = __shfl_xor_sync(0xffffffffu, h1[k], m);
            }
        // -- recurrent matmuls (separate accumulators, start at first FMA) --
        ull ra00, ra01, ra10, ra11;
        {
            const ull d0 = dup2(h0[0]);
            ra00 = ffma2(d0, w[0][0][0], 0ull * 0);  // zero-init via ffma with c=0
            ra00 = 0;  // (placeholder removed below)
        }
        // real zero-init:
        ra00 = dup2(0.f); ra01 = dup2(0.f); ra10 = dup2(0.f); ra11 = dup2(0.f);
#pragma unroll
        for (int k = 0; k < 4; k++) {
            const ull d0 = dup2(h0[k]);
            ra00 = ffma2(d0, w[0][0][k], ra00);
            ra01 = ffma2(d0, w[1][0][k], ra01);
            const ull d1 = dup2(h1[k]);
            ra10 = ffma2(d1, w[0][0][k], ra10);
            ra11 = ffma2(d1, w[1][0][k], ra11);
        }
#pragma unroll
        for (int m = 1; m < 4; m++)
#pragma unroll
            for (int k = 0; k < 4; k++) {
                const ull d0 = dup2(rv0[m - 1][k]);
                ra00 = ffma2(d0, w[0][m][k], ra00);
                ra01 = ffma2(d0, w[1][m][k], ra01);
                const ull d1 = dup2(rv1[m - 1][k]);
                ra10 = ffma2(d1, w[0][m][k], ra10);
                ra11 = ffma2(d1, w[1][m][k], ra11);
            }
        // -- combine + tanh --
        float v0, v1;
        unpack2(fadd2(pa00, ra00), v0, v1); h0[0] = tanh_pre(v0); h0[1] = tanh_pre(v1);
        unpack2(fadd2(pa01, ra01), v0, v1); h0[2] = tanh_pre(v0); h0[3] = tanh_pre(v1);
        unpack2(fadd2(pa10, ra10), v0, v1); h1[0] = tanh_pre(v0); h1[1] = tanh_pre(v1);
        unpack2(fadd2(pa11, ra11), v0, v1); h1[2] = tanh_pre(v0); h1[3] = tanh_pre(v1);
    };

    // Double-buffered CHUNK=2 prefetch per batch: 8 LDG.128 in flight.
    float4 A0[2 * CHUNK], A1[2 * CHUNK], B0[2 * CHUNK], B1[2 * CHUNK];
#pragma unroll
    for (int i = 0; i < 2 * CHUNK; i++) { A0[i] = __ldg(&xb0[i]); A1[i] = __ldg(&xb1[i]); }

    for (int c = 0; c < NCHUNK; c += 2) {
        const float4* pB0 = xb0 + (size_t)(c + 1) * 2 * CHUNK;
        const float4* pB1 = xb1 + (size_t)(c + 1) * 2 * CHUNK;
#pragma unroll
        for (int i = 0; i < 2 * CHUNK; i++) { B0[i] = __ldg(&pB0[i]); B1[i] = __ldg(&pB1[i]); }
#pragma unroll
        for (int s = 0; s < CHUNK; s++)
            stepPair(A0[2 * s], A0[2 * s + 1], A1[2 * s], A1[2 * s + 1]);

        if (c + 2 < NCHUNK) {
            const float4* pA0 = xb0 + (size_t)(c + 2) * 2 * CHUNK;
            const float4* pA1 = xb1 + (size_t)(c + 2) * 2 * CHUNK;
#pragma unroll
            for (int i = 0; i < 2 * CHUNK; i++) { A0[i] = __ldg(&pA0[i]); A1[i] = __ldg(&pA1[i]); }
        }
#pragma unroll
        for (int s = 0; s < CHUNK; s++)
            stepPair(B0[2 * s], B0[2 * s + 1], B1[2 * s], B1[2 * s + 1]);
    }

    // fc over own 4 channels for each batch, butterfly-reduce within group.
    float p0 = h0[0] * fc_w[c0 + 0] + h0[1] * fc_w[c0 + 1]
             + h0[2] * fc_w[c0 + 2] + h0[3] * fc_w[c0 + 3];
    float p1 = h1[0] * fc_w[c0 + 0] + h1[1] * fc_w[c0 + 1]
             + h1[2] * fc_w[c0 + 2] + h1[3] * fc_w[c0 + 3];
    p0 += __shfl_xor_sync(0xffffffffu, p0, 1);
    p0 += __shfl_xor_sync(0xffffffffu, p0, 2);
    p1 += __shfl_xor_sync(0xffffffffu, p1, 1);
    p1 += __shfl_xor_sync(0xffffffffu, p1, 2);
    if (sub == 0) {
        out[b0] = p0 + fc_b[0];
        out[b1] = p1 + fc_b[0];
    }
}

extern "C" void kernel_launch(void* const* d_in, const int* in_sizes, int n_in,
                              void* d_out, int out_size)
{
    const float* x    = (const float*)d_in[0];
    const float* W_ih = (const float*)d_in[1];
    const float* W_hh = (const float*)d_in[2];
    const float* b_ih = (const float*)d_in[3];
    const float* b_hh = (const float*)d_in[4];
    const float* fc_w = (const float*)d_in[5];
    const float* fc_b = (const float*)d_in[6];
    float* out = (float*)d_out;

    const int n_batch = out_size;            // 8192
    const int threads = (n_batch / 2) * 4;   // 16384 (2 batches per thread)
    const int block   = 128;                 // 4 warps -> 1 per SMSP
    const int grid    = (threads + block - 1) / block;   // 128
    rnn_fused6_kernel<<<grid, block>>>(x, W_ih, W_hh, b_ih, b_hh, fc_w, fc_b,
                                       out, n_batch);
}

// round 12
// speedup vs baseline: 1.3616x; 1.3616x over previous
#include <cuda_runtime.h>

// RNNModel: x[8192,512,8] fp32 -> out[8192] fp32.
// R9 = R7 resubmitted (R8 died to container infra, no data).
// j-packed f32x2 layout — accumulator slots hold (even j, odd j) partial
// sums, so FMA2 multiplicands are naturally packed h/x pairs: ZERO broadcast
// movs. h exchanged as packed b64 shuffles. 4 lanes/batch, 1024 one-warp
// CTAs over all 148 SMs, CHUNK=4 double-buffered x prefetch (8 LDG.128).

constexpr int T_LEN = 512;
constexpr int I_LEN = 8;
constexpr int H_LEN = 16;
constexpr int CHUNK = 4;                  // steps per buffer
constexpr int NCHUNK = T_LEN / CHUNK;     // 128

typedef unsigned long long ull;

__device__ __forceinline__ ull ffma2(ull a, ull b, ull c) {
    ull d;
    asm("fma.rn.f32x2 %0, %1, %2, %3;" : "=l"(d) : "l"(a), "l"(b), "l"(c));
    return d;
}
__device__ __forceinline__ ull fmul2(ull a, ull b) {
    ull d;
    asm("mul.rn.f32x2 %0, %1, %2;" : "=l"(d) : "l"(a), "l"(b));
    return d;
}
__device__ __forceinline__ ull fadd2(ull a, ull b) {
    ull d;
    asm("add.rn.f32x2 %0, %1, %2;" : "=l"(d) : "l"(a), "l"(b));
    return d;
}
__device__ __forceinline__ ull pack2(float x, float y) {
    ull d;
    asm("mov.b64 %0, {%1, %2};" : "=l"(d) : "f"(x), "f"(y));
    return d;
}
__device__ __forceinline__ void unpack2(ull d, float& x, float& y) {
    asm("mov.b64 {%0, %1}, %2;" : "=f"(x), "=f"(y) : "l"(d));
}

// v pre-scaled by 2*log2(e): tanh = 1 - 2/(ex2(v)+1). ~1e-7 abs err.
__device__ __forceinline__ float tanh_pre(float v) {
    float e, r;
    asm("ex2.approx.f32 %0, %1;" : "=f"(e) : "f"(v));
    asm("rcp.approx.f32 %0, %1;" : "=f"(r) : "f"(e + 1.0f));
    return fmaf(-2.0f, r, 1.0f);
}

__global__ void __launch_bounds__(32) rnn_fused9_kernel(
    const float* __restrict__ x,
    const float* __restrict__ W_ih,
    const float* __restrict__ W_hh,
    const float* __restrict__ b_ih,
    const float* __restrict__ b_hh,
    const float* __restrict__ fc_w,
    const float* __restrict__ fc_b,
    float* __restrict__ out,
    int n_batch)
{
    const int tid = blockIdx.x * blockDim.x + threadIdx.x;
    const int sub = tid & 3;          // lane within 4-lane group
    const int b   = tid >> 2;         // batch element
    if (b >= n_batch) return;
    const int c0 = sub * 4;           // own output-channel base

    const float C = 2.8853900817779268f;  // 2*log2(e) folded into weights

    // w2[i][m][q]: packed (even,odd) W_hh pair for output c0+i, input pair q
    // of the lane sub^m (m=0 own, m=1..3 remote via shfl_xor(m)).
    ull w2[4][4][2];
#pragma unroll
    for (int i = 0; i < 4; i++) {
        const int row = (c0 + i) * H_LEN;
#pragma unroll
        for (int m = 0; m < 4; m++) {
            const int cb = 4 * (sub ^ m);
#pragma unroll
            for (int q = 0; q < 2; q++)
                w2[i][m][q] = pack2(C * W_hh[row + cb + 2 * q],
                                    C * W_hh[row + cb + 2 * q + 1]);
        }
    }
    // u2[i][ip]: packed W_ih pair (inputs 2ip, 2ip+1) for output c0+i.
    ull u2[4][4];
#pragma unroll
    for (int i = 0; i < 4; i++) {
        const int row = (c0 + i) * I_LEN;
#pragma unroll
        for (int ip = 0; ip < 4; ip++)
            u2[i][ip] = pack2(C * W_ih[row + 2 * ip], C * W_ih[row + 2 * ip + 1]);
    }
    // bias in slot .x only (slot .y contributes 0 to the horizontal add).
    ull bias2[4];
#pragma unroll
    for (int i = 0; i < 4; i++)
        bias2[i] = pack2(C * (b_ih[c0 + i] + b_hh[c0 + i]), 0.0f);

    // Own hidden state, packed along j: hp[0]=(h_{c0},h_{c0+1}), hp[1]=(h_{c0+2},h_{c0+3}).
    ull hp[2] = {0ull, 0ull};

    const ulonglong2* xb =
        reinterpret_cast<const ulonglong2*>(x + (size_t)b * T_LEN * I_LEN);

    // One step; q0,q1 carry the 8 x values as 4 packed pairs (free packing).
    auto step = [&](ulonglong2 q0, ulonglong2 q1) {
        // Shuffles first (packed b64 -> 2 SHFLs each, no movs); 26-cyc latency
        // covered by the independent input projection below.
        ull rp[3][2];
#pragma unroll
        for (int m = 1; m < 4; m++) {
            rp[m - 1][0] = __shfl_xor_sync(0xffffffffu, hp[0], m);
            rp[m - 1][1] = __shfl_xor_sync(0xffffffffu, hp[1], m);
        }

        // Input projection: 16 FMA2, all operands naturally packed.
        const ull xq[4] = {q0.x, q0.y, q1.x, q1.y};
        ull pa[4];
#pragma unroll
        for (int i = 0; i < 4; i++) pa[i] = bias2[i];
#pragma unroll
        for (int ip = 0; ip < 4; ip++)
#pragma unroll
            for (int i = 0; i < 4; i++)
                pa[i] = ffma2(xq[ip], u2[i][ip], pa[i]);

        // Recurrence: own pairs first (no shfl dependency), then remote.
        ull ra[4];
#pragma unroll
        for (int i = 0; i < 4; i++) ra[i] = fmul2(hp[0], w2[i][0][0]);
#pragma unroll
        for (int i = 0; i < 4; i++) ra[i] = ffma2(hp[1], w2[i][0][1], ra[i]);
#pragma unroll
        for (int m = 1; m < 4; m++)
#pragma unroll
            for (int q = 0; q < 2; q++)
#pragma unroll
                for (int i = 0; i < 4; i++)
                    ra[i] = ffma2(rp[m - 1][q], w2[i][m][q], ra[i]);

        // Combine, horizontal add, tanh.
        float t0, t1, t2, t3;
        {
            float sx, sy;
            unpack2(fadd2(pa[0], ra[0]), sx, sy); t0 = tanh_pre(sx + sy);
            unpack2(fadd2(pa[1], ra[1]), sx, sy); t1 = tanh_pre(sx + sy);
            unpack2(fadd2(pa[2], ra[2]), sx, sy); t2 = tanh_pre(sx + sy);
            unpack2(fadd2(pa[3], ra[3]), sx, sy); t3 = tanh_pre(sx + sy);
        }
        hp[0] = pack2(t0, t1);
        hp[1] = pack2(t2, t3);
    };

    // Double-buffered CHUNK-step prefetch: 8 LDG.128 outstanding.
    ulonglong2 A[2 * CHUNK], B[2 * CHUNK];
#pragma unroll
    for (int i = 0; i < 2 * CHUNK; i++) A[i] = xb[i];

    for (int c = 0; c < NCHUNK; c += 2) {
        const ulonglong2* pB = xb + (size_t)(c + 1) * 2 * CHUNK;
#pragma unroll
        for (int i = 0; i < 2 * CHUNK; i++) B[i] = pB[i];
#pragma unroll
        for (int s = 0; s < CHUNK; s++) step(A[2 * s], A[2 * s + 1]);

        if (c + 2 < NCHUNK) {
            const ulonglong2* pA = xb + (size_t)(c + 2) * 2 * CHUNK;
#pragma unroll
            for (int i = 0; i < 2 * CHUNK; i++) A[i] = pA[i];
        }
#pragma unroll
        for (int s = 0; s < CHUNK; s++) step(B[2 * s], B[2 * s + 1]);
    }

    // fc over own 4 channels, butterfly-reduce across the 4-lane group.
    float h0, h1, h2, h3;
    unpack2(hp[0], h0, h1);
    unpack2(hp[1], h2, h3);
    float part = h0 * fc_w[c0 + 0] + h1 * fc_w[c0 + 1]
               + h2 * fc_w[c0 + 2] + h3 * fc_w[c0 + 3];
    part += __shfl_xor_sync(0xffffffffu, part, 1);
    part += __shfl_xor_sync(0xffffffffu, part, 2);
    if (sub == 0) out[b] = part + fc_b[0];
}

extern "C" void kernel_launch(void* const* d_in, const int* in_sizes, int n_in,
                              void* d_out, int out_size)
{
    const float* x    = (const float*)d_in[0];
    const float* W_ih = (const float*)d_in[1];
    const float* W_hh = (const float*)d_in[2];
    const float* b_ih = (const float*)d_in[3];
    const float* b_hh = (const float*)d_in[4];
    const float* fc_w = (const float*)d_in[5];
    const float* fc_b = (const float*)d_in[6];
    float* out = (float*)d_out;

    const int n_batch = out_size;        // 8192
    const int threads = n_batch * 4;     // 32768 (1024 warps)
    const int block   = 32;              // 1-warp CTAs -> spread over 148 SMs
    const int grid    = (threads + block - 1) / block;   // 1024
    rnn_fused9_kernel<<<grid, block>>>(x, W_ih, W_hh, b_ih, b_hh, fc_w, fc_b,
                                       out, n_batch);
}

// round 13
// speedup vs baseline: 1.4182x; 1.0416x over previous
#include <cuda_runtime.h>

// RNNModel: x[8192,512,8] fp32 -> out[8192] fp32.
// R12: R9 j-packed compute core + COOPERATIVE COALESCED x loads.
// Lanes of a 4-lane group load disjoint 16B pieces (64B contiguous per group
// per LDG -> full sectors, 4x fewer LDG instr, ~8x fewer L1tex wavefronts);
// step data redistributed via width-4 shfl broadcasts (off the h critical
// path). CHUNK=8 double-buffered (lead ~8 steps).

constexpr int T_LEN = 512;
constexpr int I_LEN = 8;
constexpr int H_LEN = 16;
constexpr int CHUNK = 8;                  // steps per buffer
constexpr int NCHUNK = T_LEN / CHUNK;     // 64
constexpr int LPC = CHUNK / 2;            // 16B loads per lane per chunk (4)

typedef unsigned long long ull;

__device__ __forceinline__ ull ffma2(ull a, ull b, ull c) {
    ull d;
    asm("fma.rn.f32x2 %0, %1, %2, %3;" : "=l"(d) : "l"(a), "l"(b), "l"(c));
    return d;
}
__device__ __forceinline__ ull fmul2(ull a, ull b) {
    ull d;
    asm("mul.rn.f32x2 %0, %1, %2;" : "=l"(d) : "l"(a), "l"(b));
    return d;
}
__device__ __forceinline__ ull fadd2(ull a, ull b) {
    ull d;
    asm("add.rn.f32x2 %0, %1, %2;" : "=l"(d) : "l"(a), "l"(b));
    return d;
}
__device__ __forceinline__ ull pack2(float x, float y) {
    ull d;
    asm("mov.b64 %0, {%1, %2};" : "=l"(d) : "f"(x), "f"(y));
    return d;
}
__device__ __forceinline__ void unpack2(ull d, float& x, float& y) {
    asm("mov.b64 {%0, %1}, %2;" : "=f"(x), "=f"(y) : "l"(d));
}

// v pre-scaled by 2*log2(e): tanh = 1 - 2/(ex2(v)+1). ~1e-7 abs err.
__device__ __forceinline__ float tanh_pre(float v) {
    float e, r;
    asm("ex2.approx.f32 %0, %1;" : "=f"(e) : "f"(v));
    asm("rcp.approx.f32 %0, %1;" : "=f"(r) : "f"(e + 1.0f));
    return fmaf(-2.0f, r, 1.0f);
}

__global__ void __launch_bounds__(32) rnn_fused12_kernel(
    const float* __restrict__ x,
    const float* __restrict__ W_ih,
    const float* __restrict__ W_hh,
    const float* __restrict__ b_ih,
    const float* __restrict__ b_hh,
    const float* __restrict__ fc_w,
    const float* __restrict__ fc_b,
    float* __restrict__ out,
    int n_batch)
{
    const int tid = blockIdx.x * blockDim.x + threadIdx.x;
    const int sub = tid & 3;          // lane within 4-lane group
    const int b   = tid >> 2;         // batch element
    if (b >= n_batch) return;
    const int c0 = sub * 4;           // own output-channel base

    const float C = 2.8853900817779268f;  // 2*log2(e) folded into weights

    // w2[i][m][q]: packed (even,odd) W_hh pair for output c0+i, input pair q
    // of the lane sub^m (m=0 own, m=1..3 remote via shfl_xor(m)).
    ull w2[4][4][2];
#pragma unroll
    for (int i = 0; i < 4; i++) {
        const int row = (c0 + i) * H_LEN;
#pragma unroll
        for (int m = 0; m < 4; m++) {
            const int cb = 4 * (sub ^ m);
#pragma unroll
            for (int q = 0; q < 2; q++)
                w2[i][m][q] = pack2(C * W_hh[row + cb + 2 * q],
                                    C * W_hh[row + cb + 2 * q + 1]);
        }
    }
    // u2[i][ip]: packed W_ih pair (inputs 2ip, 2ip+1) for output c0+i.
    ull u2[4][4];
#pragma unroll
    for (int i = 0; i < 4; i++) {
        const int row = (c0 + i) * I_LEN;
#pragma unroll
        for (int ip = 0; ip < 4; ip++)
            u2[i][ip] = pack2(C * W_ih[row + 2 * ip], C * W_ih[row + 2 * ip + 1]);
    }
    // bias in slot .x only (slot .y contributes 0 to the horizontal add).
    ull bias2[4];
#pragma unroll
    for (int i = 0; i < 4; i++)
        bias2[i] = pack2(C * (b_ih[c0 + i] + b_hh[c0 + i]), 0.0f);

    // Own hidden state packed along j.
    ull hp[2] = {0ull, 0ull};

    // Cooperative load base: batch row as 16B units (1024 per batch).
    const ulonglong2* xb =
        reinterpret_cast<const ulonglong2*>(x + (size_t)b * T_LEN * I_LEN);

    // One step; piece indices are compile-time within the unrolled chunk.
    // buf[r] holds this lane's pieces 4r+sub of the chunk.
    auto step = [&](const ulonglong2* buf, int s) {
        // -- broadcast step's two 16B pieces from their owner lanes --
        const int p0 = 2 * s, p1 = 2 * s + 1;
        const int r0 = p0 >> 2, o0 = p0 & 3;
        const int r1 = p1 >> 2, o1 = p1 & 3;
        ull xq0 = __shfl_sync(0xffffffffu, buf[r0].x, o0, 4);
        ull xq1 = __shfl_sync(0xffffffffu, buf[r0].y, o0, 4);
        ull xq2 = __shfl_sync(0xffffffffu, buf[r1].x, o1, 4);
        ull xq3 = __shfl_sync(0xffffffffu, buf[r1].y, o1, 4);

        // -- h exchange (critical path start) --
        ull rp[3][2];
#pragma unroll
        for (int m = 1; m < 4; m++) {
            rp[m - 1][0] = __shfl_xor_sync(0xffffffffu, hp[0], m);
            rp[m - 1][1] = __shfl_xor_sync(0xffffffffu, hp[1], m);
        }

        // -- input projection (depends only on x broadcasts) --
        const ull xq[4] = {xq0, xq1, xq2, xq3};
        ull pa[4];
#pragma unroll
        for (int i = 0; i < 4; i++) pa[i] = bias2[i];
#pragma unroll
        for (int ip = 0; ip < 4; ip++)
#pragma unroll
            for (int i = 0; i < 4; i++)
                pa[i] = ffma2(xq[ip], u2[i][ip], pa[i]);

        // -- recurrence: own pairs first, then remote --
        ull ra[4];
#pragma unroll
        for (int i = 0; i < 4; i++) ra[i] = fmul2(hp[0], w2[i][0][0]);
#pragma unroll
        for (int i = 0; i < 4; i++) ra[i] = ffma2(hp[1], w2[i][0][1], ra[i]);
#pragma unroll
        for (int m = 1; m < 4; m++)
#pragma unroll
            for (int q = 0; q < 2; q++)
#pragma unroll
                for (int i = 0; i < 4; i++)
                    ra[i] = ffma2(rp[m - 1][q], w2[i][m][q], ra[i]);

        // -- combine, horizontal add, tanh --
        float t0, t1, t2, t3;
        {
            float sx, sy;
            unpack2(fadd2(pa[0], ra[0]), sx, sy); t0 = tanh_pre(sx + sy);
            unpack2(fadd2(pa[1], ra[1]), sx, sy); t1 = tanh_pre(sx + sy);
            unpack2(fadd2(pa[2], ra[2]), sx, sy); t2 = tanh_pre(sx + sy);
            unpack2(fadd2(pa[3], ra[3]), sx, sy); t3 = tanh_pre(sx + sy);
        }
        hp[0] = pack2(t0, t1);
        hp[1] = pack2(t2, t3);
    };

    // Double-buffered chunks; lane loads LPC disjoint 16B pieces per chunk.
    // Chunk c occupies piece indices [16c, 16c+16); lane takes 16c + 4r + sub.
    ulonglong2 A[LPC], B[LPC];
#pragma unroll
    for (int r = 0; r < LPC; r++) A[r] = xb[4 * r + sub];

    for (int c = 0; c < NCHUNK; c += 2) {
        const int baseB = 2 * CHUNK * (c + 1);
#pragma unroll
        for (int r = 0; r < LPC; r++) B[r] = xb[baseB + 4 * r + sub];
#pragma unroll
        for (int s = 0; s < CHUNK; s++) step(A, s);

        if (c + 2 < NCHUNK) {
            const int baseA = 2 * CHUNK * (c + 2);
#pragma unroll
            for (int r = 0; r < LPC; r++) A[r] = xb[baseA + 4 * r + sub];
        }
#pragma unroll
        for (int s = 0; s < CHUNK; s++) step(B, s);
    }

    // fc over own 4 channels, butterfly-reduce across the 4-lane group.
    float h0, h1, h2, h3;
    unpack2(hp[0], h0, h1);
    unpack2(hp[1], h2, h3);
    float part = h0 * fc_w[c0 + 0] + h1 * fc_w[c0 + 1]
               + h2 * fc_w[c0 + 2] + h3 * fc_w[c0 + 3];
    part += __shfl_xor_sync(0xffffffffu, part, 1);
    part += __shfl_xor_sync(0xffffffffu, part, 2);
    if (sub == 0) out[b] = part + fc_b[0];
}

extern "C" void kernel_launch(void* const* d_in, const int* in_sizes, int n_in,
                              void* d_out, int out_size)
{
    const float* x    = (const float*)d_in[0];
    const float* W_ih = (const float*)d_in[1];
    const float* W_hh = (const float*)d_in[2];
    const float* b_ih = (const float*)d_in[3];
    const float* b_hh = (const float*)d_in[4];
    const float* fc_w = (const float*)d_in[5];
    const float* fc_b = (const float*)d_in[6];
    float* out = (float*)d_out;

    const int n_batch = out_size;        // 8192
    const int threads = n_batch * 4;     // 32768 (1024 warps)
    const int block   = 32;              // 1-warp CTAs spread over 148 SMs
    const int grid    = (threads + block - 1) / block;   // 1024
    rnn_fused12_kernel<<<grid, block>>>(x, W_ih, W_hh, b_ih, b_hh, fc_w, fc_b,
                                        out, n_batch);
}